// round 8
// baseline (speedup 1.0000x reference)
#include <cuda_runtime.h>
#include <cstdint>
#include <cstddef>

// Problem constants (fixed by the dataset)
#define B_  32
#define N_  1024
#define D_  128
#define C_  16
// P*P = 16, Hg = 32, out image 128x128 per (b,c)

// One warp per CTA; warp handles 64 token rows (lane l -> rows l and l+32).
#define THREADS 32

// Dynamic shared layout (floats)
#define XBUF_OFF   0                   // [64][128] swizzled x rows   (32KB)
#define WBUF_OFF   (64 * D_)           // 8192: [16][128] swizzled W  (8KB)
#define STAGE_OFF  (WBUF_OFF + 16*D_)  // 10240: [2][1024] store staging (8KB)
#define SCBM_OFF   (STAGE_OFF + 2048)  // 12288: [256]
#define SMASK_OFF  (SCBM_OFF + 256)    // 12544: [16]
#define SMEM_FLOATS (SMASK_OFF + 16)   // 12560
#define SMEM_BYTES  (SMEM_FLOATS * 4)  // 50240 -> 4 CTAs/SM

// Precomputed channel table: cb[c*16+p] = emb[c]·W[p] + bias[p]
__device__ float g_cb[C_ * 16];

__device__ __forceinline__ uint32_t smem_u32(const void* p) {
    return (uint32_t)__cvta_generic_to_shared(p);
}

// Blackwell packed fp32x2 FMA (PTX-only)
#define FMA_F32X2(d, a, b, c) \
    asm("fma.rn.f32x2 %0, %1, %2, %3;" : "=l"(d) : "l"(a), "l"(b), "l"(c))

// ---------------------------------------------------------------------------
// Kernel A: build the 16x16 channel table once (one warp per entry).
// ---------------------------------------------------------------------------
__global__ void __launch_bounds__(1024, 1)
cb_table_kernel(const float* __restrict__ emb,   // [256, D]
                const float* __restrict__ W,     // [16, D]
                const float* __restrict__ bias)  // [16]
{
    const int w = (blockIdx.x * blockDim.x + threadIdx.x) >> 5;  // 0..255
    const int l = threadIdx.x & 31;
    const int c = w >> 4, p = w & 15;

    float4 e = *reinterpret_cast<const float4*>(emb + (size_t)c * D_ + l * 4);
    float4 v = *reinterpret_cast<const float4*>(W   + (size_t)p * D_ + l * 4);
    float s = e.x * v.x + e.y * v.y + e.z * v.z + e.w * v.w;
    #pragma unroll
    for (int off = 16; off > 0; off >>= 1)
        s += __shfl_xor_sync(0xffffffffu, s, off);
    if (l == 0) g_cb[w] = s + bias[p];
}

// ---------------------------------------------------------------------------
// Kernel B: warp-autonomous, 2 rows/lane, bulk-store epilogue.
// ---------------------------------------------------------------------------
__global__ void __launch_bounds__(THREADS)
QBD_main_kernel(
    const float* __restrict__ x,     // [B, N, D]
    const float* __restrict__ pmask, // [B, C]
    const float* __restrict__ W,     // [16, D]
    float* __restrict__ out)         // [B, C, 128, 128]
{
    extern __shared__ float sm[];
    float* xbuf  = sm + XBUF_OFF;
    float* wbuf  = sm + WBUF_OFF;
    float* stage = sm + STAGE_OFF;
    float* scbm  = sm + SCBM_OFF;
    float* smask = sm + SMASK_OFF;

    const int l     = threadIdx.x;
    const int chunk = blockIdx.x;            // 0..511, 64 rows each
    const int b     = chunk >> 4;            // batch
    const int hg0   = (chunk & 15) << 1;     // first of 2 row-groups

    // ---- Stage 64 x rows (32KB, contiguous) via cp.async, swizzled:
    //      phys 16B-chunk col = lane ^ (row & 7) ----
    const float4* gx = reinterpret_cast<const float4*>(x + (size_t)chunk * 64 * D_);
    #pragma unroll
    for (int i = 0; i < 64; ++i) {
        uint32_t dst = smem_u32(xbuf + i * D_ + ((l ^ (i & 7)) << 2));
        asm volatile("cp.async.cg.shared.global [%0], [%1], 16;\n"
                     :: "r"(dst), "l"(gx + i * 32 + l));
    }
    // ---- Stage W (8KB), same swizzle keyed by W row ----
    const float4* gw = reinterpret_cast<const float4*>(W);
    #pragma unroll
    for (int i = 0; i < 16; ++i) {
        uint32_t dst = smem_u32(wbuf + i * D_ + ((l ^ (i & 7)) << 2));
        asm volatile("cp.async.cg.shared.global [%0], [%1], 16;\n"
                     :: "r"(dst), "l"(gw + i * 32 + l));
    }
    asm volatile("cp.async.commit_group;\n");

    // ---- Mask-premultiplied channel table (overlaps DRAM flight) ----
    #pragma unroll
    for (int i = 0; i < 8; ++i) {
        int idx = i * 32 + l;
        scbm[idx] = g_cb[idx] * pmask[b * C_ + (idx >> 4)];
    }
    if (l < C_) smask[l] = pmask[b * C_ + l];

    asm volatile("cp.async.wait_group 0;\n");
    __syncwarp();

    // ---- Main dot products: rows A=l, B=l+32, all 16 p's, packed over d.
    //      xv: conflict-free (keys l&7); wv: warp-uniform broadcast,
    //      SHARED by both rows -> wv LDS per row halved. ----
    const float* xrA = xbuf + l * D_;
    const float* xrB = xbuf + (l + 32) * D_;
    const int    xs  = l & 7;

    unsigned long long accA[16], accB[16];
    #pragma unroll
    for (int j = 0; j < 16; ++j) { accA[j] = 0ull; accB[j] = 0ull; }

    #pragma unroll
    for (int d4 = 0; d4 < 32; ++d4) {
        const int off = (d4 ^ xs) << 2;
        ulonglong2 xvA = *reinterpret_cast<const ulonglong2*>(xrA + off);
        ulonglong2 xvB = *reinterpret_cast<const ulonglong2*>(xrB + off);
        #pragma unroll
        for (int j = 0; j < 16; ++j) {
            const ulonglong2 wv = *reinterpret_cast<const ulonglong2*>(
                wbuf + j * D_ + ((d4 ^ (j & 7)) << 2));
            FMA_F32X2(accA[j], xvA.x, wv.x, accA[j]);
            FMA_F32X2(accA[j], xvA.y, wv.y, accA[j]);
            FMA_F32X2(accB[j], xvB.x, wv.x, accB[j]);
            FMA_F32X2(accB[j], xvB.y, wv.y, accB[j]);
        }
    }

    // ---- Horizontal add (even+odd d), re-pack pairs (p-adjacent) ----
    unsigned long long xa2A[8], xa2B[8];
    #pragma unroll
    for (int k = 0; k < 8; ++k) {
        uint32_t a0, a1, b0, b1, t0, t1;
        asm("mov.b64 {%0, %1}, %2;" : "=r"(a0), "=r"(t0) : "l"(accA[2*k]));
        asm("mov.b64 {%0, %1}, %2;" : "=r"(a1), "=r"(t1) : "l"(accA[2*k+1]));
        float fa0 = __uint_as_float(a0) + __uint_as_float(t0);
        float fa1 = __uint_as_float(a1) + __uint_as_float(t1);
        asm("mov.b64 %0, {%1, %2};" : "=l"(xa2A[k])
            : "r"(__float_as_uint(fa0)), "r"(__float_as_uint(fa1)));
        asm("mov.b64 {%0, %1}, %2;" : "=r"(b0), "=r"(t0) : "l"(accB[2*k]));
        asm("mov.b64 {%0, %1}, %2;" : "=r"(b1), "=r"(t1) : "l"(accB[2*k+1]));
        float fb0 = __uint_as_float(b0) + __uint_as_float(t0);
        float fb1 = __uint_as_float(b1) + __uint_as_float(t1);
        asm("mov.b64 %0, {%1, %2};" : "=l"(xa2B[k])
            : "r"(__float_as_uint(fb0)), "r"(__float_as_uint(fb1)));
    }

    // ---- Epilogue: per channel, build a 4KB tile (8 image rows x 128 cols)
    //      in smem (STS.128, conflict-free), then ONE cp.async.bulk store.
    //      Double-buffered; bulk group drained with wait_group.read. ----
    #pragma unroll
    for (int c = 0; c < C_; ++c) {
        if (c >= 2) {
            asm volatile("cp.async.bulk.wait_group.read 1;\n" ::: "memory");
        }
        __syncwarp();

        float* st = stage + (c & 1) * 1024;
        float  m  = smask[c];
        unsigned long long m2;
        asm("mov.b64 %0, {%1, %1};" : "=l"(m2) : "r"(__float_as_uint(m)));

        #pragma unroll
        for (int pr = 0; pr < 4; ++pr) {
            ulonglong2 cb = *reinterpret_cast<const ulonglong2*>(scbm + c * 16 + pr * 4);
            ulonglong2 vA, vB;
            FMA_F32X2(vA.x, xa2A[pr * 2],     m2, cb.x);
            FMA_F32X2(vA.y, xa2A[pr * 2 + 1], m2, cb.y);
            FMA_F32X2(vB.x, xa2B[pr * 2],     m2, cb.x);
            FMA_F32X2(vB.y, xa2B[pr * 2 + 1], m2, cb.y);
            *reinterpret_cast<ulonglong2*>(st + pr * 128 + l * 4)       = vA;  // row-group hg0
            *reinterpret_cast<ulonglong2*>(st + (4 + pr) * 128 + l * 4) = vB;  // row-group hg0+1
        }
        __syncwarp();

        if (l == 0) {
            asm volatile("fence.proxy.async.shared::cta;\n" ::: "memory");
            const float* gdst = out + ((size_t)(b * C_ + c)) * (128 * 128) + hg0 * 512;
            asm volatile("cp.async.bulk.global.shared::cta.bulk_group [%0], [%1], %2;\n"
                         :: "l"(gdst), "r"(smem_u32(st)), "r"(4096) : "memory");
            asm volatile("cp.async.bulk.commit_group;\n" ::: "memory");
        }
    }
    // Drain all bulk stores before exit.
    if (l == 0)
        asm volatile("cp.async.bulk.wait_group 0;\n" ::: "memory");
}

extern "C" void kernel_launch(void* const* d_in, const int* in_sizes, int n_in,
                              void* d_out, int out_size)
{
    const float* x    = (const float*)d_in[0];  // [32,1024,128]
    const float* pm   = (const float*)d_in[1];  // [32,16]
    const float* emb  = (const float*)d_in[2];  // [256,128]
    const float* W    = (const float*)d_in[3];  // [16,128]
    const float* bias = (const float*)d_in[4];  // [16]
    float* out        = (float*)d_out;          // [32,16,128,128]

    // Kernel A: 256-entry channel table (one warp per entry)
    cb_table_kernel<<<8, 1024>>>(emb, W, bias);

    // Kernel B: 512 single-warp CTAs, 64 rows each
    cudaFuncSetAttribute(QBD_main_kernel,
                         cudaFuncAttributeMaxDynamicSharedMemorySize, SMEM_BYTES);
    QBD_main_kernel<<<512, THREADS, SMEM_BYTES>>>(x, pm, W, out);
}